// round 2
// baseline (speedup 1.0000x reference)
#include <cuda_runtime.h>
#include <cuda_bf16.h>

#define NP 8192
#define TI 256              // threads per block
#define IBLK 2              // i-particles per thread
#define IPB (TI * IBLK)     // 512 i per block
#define TJ 256              // j-particles per block chunk
#define NSPLIT (NP / TJ)    // 32 j-chunks
#define GX (NP / IPB)       // 16

#define INV_H 10.0f
#define H2    0.01f
#define EPS   1e-10f
#define SLACK 1e-3f         // screen slack >> cancellation error (~1e-5)

// 8 / (PI * H^3) — matches reference constant
__device__ __constant__ float kNorm = (float)(8.0 / (3.14159265 * 0.001));

__global__ void init_out_kernel(float* __restrict__ out) {
    int i = blockIdx.x * blockDim.x + threadIdx.x;
    if (i < NP) out[i] = 0.0f;
}

// Exact per-pair contribution (rare path; only for screened groups).
__device__ __forceinline__ void exact_pair(float4 p, float xi, float yi, float zi,
                                           float& acc)
{
    float dx = p.x - xi;
    float dy = p.y - yi;
    float dz = p.z - zi;
    float r2 = fmaf(dx, dx, fmaf(dy, dy, fmaf(dz, dz, EPS)));
    float r;
    asm("sqrt.approx.f32 %0, %1;" : "=f"(r) : "f"(r2));
    float q   = r * INV_H;
    float qm1 = q - 1.0f;
    float wi  = fmaf(q * q * 6.0f, qm1, 1.0f);   // 1 - 6q^2 + 6q^3
    float wo  = -2.0f * qm1 * qm1 * qm1;         // 2(1-q)^3
    float w   = (q <= 0.5f) ? wi : wo;
    acc += (q <= 1.0f) ? w : 0.0f;
}

__global__ void __launch_bounds__(TI) sph_density_kernel(
    const float* __restrict__ pos, float* __restrict__ out)
{
    __shared__ float4 sj[TJ];

    const int tid = threadIdx.x;
    const int i0  = blockIdx.x * IPB + tid;
    const int i1  = i0 + TI;
    const int j0  = blockIdx.y * TJ;

    // Cooperative load of j-chunk; w component carries |pj|^2.
    for (int t = tid; t < TJ; t += TI) {
        const float* p = pos + 3 * (j0 + t);
        float px = p[0], py = p[1], pz = p[2];
        float n2 = fmaf(px, px, fmaf(py, py, pz * pz));
        sj[t] = make_float4(px, py, pz, n2);
    }
    __syncthreads();

    const float x0 = pos[3 * i0 + 0], y0 = pos[3 * i0 + 1], z0 = pos[3 * i0 + 2];
    const float x1 = pos[3 * i1 + 0], y1 = pos[3 * i1 + 1], z1 = pos[3 * i1 + 2];

    const float a0 = -2.0f * x0, b0 = -2.0f * y0, c0 = -2.0f * z0;
    const float a1 = -2.0f * x1, b1 = -2.0f * y1, c1 = -2.0f * z1;
    const float ci0 = fmaf(x0, x0, fmaf(y0, y0, z0 * z0));
    const float ci1 = fmaf(x1, x1, fmaf(y1, y1, z1 * z1));
    // screen: t + ci <= H2 + slack  <=>  t <= th
    const float th  = fmaxf(H2 + SLACK - ci0, H2 + SLACK - ci1);

    float acc0 = 0.0f, acc1 = 0.0f;

    #pragma unroll 2
    for (int t = 0; t < TJ; t += 4) {
        float4 p[4];
        #pragma unroll
        for (int u = 0; u < 4; u++) p[u] = sj[t + u];

        float s0[4], s1[4];
        #pragma unroll
        for (int u = 0; u < 4; u++) {
            // |pi|^2 folded into threshold; 3 FFMA per pair
            s0[u] = fmaf(p[u].z, c0, fmaf(p[u].y, b0, fmaf(p[u].x, a0, p[u].w)));
            s1[u] = fmaf(p[u].z, c1, fmaf(p[u].y, b1, fmaf(p[u].x, a1, p[u].w)));
        }
        float m0 = fminf(fminf(s0[0], s0[1]), fminf(s0[2], s0[3]));
        float m1 = fminf(fminf(s1[0], s1[1]), fminf(s1[2], s1[3]));
        float mm = fminf(m0, m1);

        if (__any_sync(0xFFFFFFFFu, mm <= th)) {
            #pragma unroll
            for (int u = 0; u < 4; u++) {
                exact_pair(p[u], x0, y0, z0, acc0);
                exact_pair(p[u], x1, y1, z1, acc1);
            }
        }
    }

    atomicAdd(&out[i0], acc0 * kNorm);
    atomicAdd(&out[i1], acc1 * kNorm);
}

extern "C" void kernel_launch(void* const* d_in, const int* in_sizes, int n_in,
                              void* d_out, int out_size)
{
    const float* pos = (const float*)d_in[0];
    float* out = (float*)d_out;
    (void)in_sizes; (void)n_in; (void)out_size;

    init_out_kernel<<<(NP + 255) / 256, 256>>>(out);
    sph_density_kernel<<<dim3(GX, NSPLIT), TI>>>(pos, out);
}

// round 3
// speedup vs baseline: 2.7532x; 2.7532x over previous
#include <cuda_runtime.h>
#include <cuda_bf16.h>

#define NP 8192
#define TI 256              // threads per block
#define IBLK 2              // i-particles per thread
#define IPB (TI * IBLK)     // 512 i per block
#define TJ 256              // j-particles per block chunk
#define NSPLIT (NP / TJ)    // 32 j-chunks
#define GX (NP / IPB)       // 16

#define INV_H 10.0f
#define H2    0.01f
#define EPS   1e-10f
#define SLACK 1e-3f         // screen slack >> dot-form cancellation error (~2e-6)

// 8 / (PI * H^3) — matches reference constant
__device__ __constant__ float kNorm = (float)(8.0 / (3.14159265 * 0.001));

__global__ void init_out_kernel(float* __restrict__ out) {
    int i = blockIdx.x * blockDim.x + threadIdx.x;
    if (i < NP) out[i] = 0.0f;
}

// Exact per-pair contribution (rare path; only for screened groups).
__device__ __forceinline__ void exact_pair(float4 p, float xi, float yi, float zi,
                                           float& acc)
{
    float dx = p.x - xi;
    float dy = p.y - yi;
    float dz = p.z - zi;
    float r2 = fmaf(dx, dx, fmaf(dy, dy, fmaf(dz, dz, EPS)));
    float r;
    asm("sqrt.approx.f32 %0, %1;" : "=f"(r) : "f"(r2));
    float q   = r * INV_H;
    float qm1 = q - 1.0f;
    float wi  = fmaf(q * q * 6.0f, qm1, 1.0f);   // 1 - 6q^2 + 6q^3
    float wo  = -2.0f * qm1 * qm1 * qm1;         // 2(1-q)^3
    float w   = (q <= 0.5f) ? wi : wo;
    acc += (q <= 1.0f) ? w : 0.0f;
}

__global__ void __launch_bounds__(TI) sph_density_kernel(
    const float* __restrict__ pos, float* __restrict__ out)
{
    __shared__ float4 sj[TJ];

    const int tid = threadIdx.x;
    const int i0  = blockIdx.x * IPB + tid;
    const int i1  = i0 + TI;
    const int j0  = blockIdx.y * TJ;

    // Cooperative load of j-chunk; w component carries |pj|^2.
    for (int t = tid; t < TJ; t += TI) {
        const float* p = pos + 3 * (j0 + t);
        float px = p[0], py = p[1], pz = p[2];
        float n2 = fmaf(px, px, fmaf(py, py, pz * pz));
        sj[t] = make_float4(px, py, pz, n2);
    }
    __syncthreads();

    const float x0 = pos[3 * i0 + 0], y0 = pos[3 * i0 + 1], z0 = pos[3 * i0 + 2];
    const float x1 = pos[3 * i1 + 0], y1 = pos[3 * i1 + 1], z1 = pos[3 * i1 + 2];

    const float a0 = -2.0f * x0, b0 = -2.0f * y0, c0 = -2.0f * z0;
    const float a1 = -2.0f * x1, b1 = -2.0f * y1, c1 = -2.0f * z1;
    const float ci0 = fmaf(x0, x0, fmaf(y0, y0, z0 * z0));
    const float ci1 = fmaf(x1, x1, fmaf(y1, y1, z1 * z1));
    // screen per i: s + ci <= H2 + slack  <=>  s <= th_i   (NO cross-i merge)
    const float th0 = H2 + SLACK - ci0;
    const float th1 = H2 + SLACK - ci1;

    float acc0 = 0.0f, acc1 = 0.0f;

    #pragma unroll 2
    for (int t = 0; t < TJ; t += 4) {
        float4 p[4];
        #pragma unroll
        for (int u = 0; u < 4; u++) p[u] = sj[t + u];

        float s0[4], s1[4];
        #pragma unroll
        for (int u = 0; u < 4; u++) {
            // s = |pj|^2 - 2 pi . pj  (|pi|^2 folded into threshold); 3 FFMA/pair
            s0[u] = fmaf(p[u].z, c0, fmaf(p[u].y, b0, fmaf(p[u].x, a0, p[u].w)));
            s1[u] = fmaf(p[u].z, c1, fmaf(p[u].y, b1, fmaf(p[u].x, a1, p[u].w)));
        }
        float m0 = fminf(fminf(s0[0], s0[1]), fminf(s0[2], s0[3]));
        float m1 = fminf(fminf(s1[0], s1[1]), fminf(s1[2], s1[3]));

        if (__any_sync(0xFFFFFFFFu, m0 <= th0)) {
            #pragma unroll
            for (int u = 0; u < 4; u++) exact_pair(p[u], x0, y0, z0, acc0);
        }
        if (__any_sync(0xFFFFFFFFu, m1 <= th1)) {
            #pragma unroll
            for (int u = 0; u < 4; u++) exact_pair(p[u], x1, y1, z1, acc1);
        }
    }

    atomicAdd(&out[i0], acc0 * kNorm);
    atomicAdd(&out[i1], acc1 * kNorm);
}

extern "C" void kernel_launch(void* const* d_in, const int* in_sizes, int n_in,
                              void* d_out, int out_size)
{
    const float* pos = (const float*)d_in[0];
    float* out = (float*)d_out;
    (void)in_sizes; (void)n_in; (void)out_size;

    init_out_kernel<<<(NP + 255) / 256, 256>>>(out);
    sph_density_kernel<<<dim3(GX, NSPLIT), TI>>>(pos, out);
}

// round 4
// speedup vs baseline: 3.0939x; 1.1238x over previous
#include <cuda_runtime.h>
#include <cuda_bf16.h>

#define NP 8192
#define GD 64                      // cells per dimension
#define NCELLS (GD * GD * GD)      // 262144
#define CAP 20                     // slots per cell (lambda_max ~ 4.2)
#define CELL_INV 5.0f              // 1 / 0.2
#define GMIN 6.4f                  // grid covers [-6.4, 6.4)
#define INV_H 10.0f
#define EPS 1e-10f

// 8 / (PI * H^3) — matches reference constant
__device__ __constant__ float kNorm = (float)(8.0 / (3.14159265 * 0.001));

__device__ int    d_cnt[NCELLS];
__device__ float4 d_slot[NCELLS * CAP];

__device__ __forceinline__ int cell_coord(float v) {
    int c = __float2int_rd((v + GMIN) * CELL_INV);
    return min(max(c, 0), GD - 1);
}

__global__ void zero_cnt_kernel() {
    int t = blockIdx.x * blockDim.x + threadIdx.x;   // NCELLS/4 threads
    reinterpret_cast<int4*>(d_cnt)[t] = make_int4(0, 0, 0, 0);
}

__global__ void build_kernel(const float* __restrict__ pos) {
    int i = blockIdx.x * blockDim.x + threadIdx.x;
    if (i >= NP) return;
    float x = pos[3 * i + 0], y = pos[3 * i + 1], z = pos[3 * i + 2];
    int c = (cell_coord(z) * GD + cell_coord(y)) * GD + cell_coord(x);
    int slot = atomicAdd(&d_cnt[c], 1);
    if (slot < CAP) d_slot[c * CAP + slot] = make_float4(x, y, z, 0.0f);
}

// 4 threads per particle; thread s of the quad handles stencil cells s, s+4, ...
__global__ void __launch_bounds__(128) query_kernel(
    const float* __restrict__ pos, float* __restrict__ out)
{
    int t = blockIdx.x * blockDim.x + threadIdx.x;   // NP*4 threads
    int i = t >> 2;
    int s = t & 3;

    const float xi = pos[3 * i + 0];
    const float yi = pos[3 * i + 1];
    const float zi = pos[3 * i + 2];
    const int ix = cell_coord(xi), iy = cell_coord(yi), iz = cell_coord(zi);

    float acc = 0.0f;

    #pragma unroll
    for (int k = 0; k < 27; k += 4) {
        int kk = k + s;                    // 24..27 handled: kk<27 guard
        if (kk >= 27) break;
        int dz = kk / 9, rem = kk - dz * 9;
        int dy = rem / 3, dx = rem - dy * 3;
        int cx = ix + dx - 1, cy = iy + dy - 1, cz = iz + dz - 1;
        if ((unsigned)cx >= GD || (unsigned)cy >= GD || (unsigned)cz >= GD)
            continue;
        int c = (cz * GD + cy) * GD + cx;
        int n = min(d_cnt[c], CAP);
        const float4* sp = &d_slot[c * CAP];
        for (int e = 0; e < n; e++) {
            float4 p = sp[e];
            float ddx = p.x - xi;
            float ddy = p.y - yi;
            float ddz = p.z - zi;
            float r2 = fmaf(ddx, ddx, fmaf(ddy, ddy, fmaf(ddz, ddz, EPS)));
            float r;
            asm("sqrt.approx.f32 %0, %1;" : "=f"(r) : "f"(r2));
            float q   = r * INV_H;
            float qm1 = q - 1.0f;
            float wi  = fmaf(q * q * 6.0f, qm1, 1.0f);   // 1 - 6q^2 + 6q^3
            float wo  = -2.0f * qm1 * qm1 * qm1;         // 2(1-q)^3
            float w   = (q <= 0.5f) ? wi : wo;
            acc += (q <= 1.0f) ? w : 0.0f;
        }
    }

    // reduce the quad (lanes s=0..3 of the same particle, same warp)
    acc += __shfl_xor_sync(0xFFFFFFFFu, acc, 1);
    acc += __shfl_xor_sync(0xFFFFFFFFu, acc, 2);
    if (s == 0) out[i] = acc * kNorm;
}

extern "C" void kernel_launch(void* const* d_in, const int* in_sizes, int n_in,
                              void* d_out, int out_size)
{
    const float* pos = (const float*)d_in[0];
    float* out = (float*)d_out;
    (void)in_sizes; (void)n_in; (void)out_size;

    zero_cnt_kernel<<<NCELLS / 4 / 256, 256>>>();
    build_kernel<<<NP / 128, 128>>>(pos);
    query_kernel<<<NP * 4 / 128, 128>>>(pos, out);
}

// round 5
// speedup vs baseline: 5.4511x; 1.7619x over previous
#include <cuda_runtime.h>
#include <cuda_bf16.h>

#define NP 8192
#define GD 48                      // cells per dimension
#define NCELLS (GD * GD * GD)      // 110592
#define CAP 20                     // slots per cell (lambda_max ~ 4.2)
#define CELL_INV 5.0f              // 1 / 0.2
#define GMIN 4.8f                  // grid covers [-4.8, 4.8), outliers clamp (safe)
#define INV_H 10.0f
#define EPS 1e-10f

// 8 / (PI * H^3) — matches reference constant
__device__ __constant__ float kNorm = (float)(8.0 / (3.14159265 * 0.001));

__device__ int    d_cnt[NCELLS];
__device__ float4 d_slot[NCELLS * CAP];

__device__ __forceinline__ int cell_coord(float v) {
    int c = __float2int_rd((v + GMIN) * CELL_INV);
    return min(max(c, 0), GD - 1);
}

__global__ void zero_cnt_kernel() {
    int t = blockIdx.x * blockDim.x + threadIdx.x;   // NCELLS/4 threads
    reinterpret_cast<int4*>(d_cnt)[t] = make_int4(0, 0, 0, 0);
}

__global__ void build_kernel(const float* __restrict__ pos) {
    int i = blockIdx.x * blockDim.x + threadIdx.x;
    if (i >= NP) return;
    float x = pos[3 * i + 0], y = pos[3 * i + 1], z = pos[3 * i + 2];
    int c = (cell_coord(z) * GD + cell_coord(y)) * GD + cell_coord(x);
    int slot = atomicAdd(&d_cnt[c], 1);
    if (slot < CAP) d_slot[c * CAP + slot] = make_float4(x, y, z, 0.0f);
}

// One full warp per particle: lane k (k<27) owns stencil cell k.
// All 27 cnt loads issue in parallel; slot loads are independent -> MLP high.
__global__ void __launch_bounds__(256) query_kernel(
    const float* __restrict__ pos, float* __restrict__ out)
{
    int t    = blockIdx.x * blockDim.x + threadIdx.x;   // NP*32 threads
    int i    = t >> 5;
    int lane = t & 31;

    const float xi = pos[3 * i + 0];
    const float yi = pos[3 * i + 1];
    const float zi = pos[3 * i + 2];
    const int ix = cell_coord(xi), iy = cell_coord(yi), iz = cell_coord(zi);

    float acc = 0.0f;

    if (lane < 27) {
        int dz = lane / 9, rem = lane - dz * 9;
        int dy = rem / 3,  dx  = rem - dy * 3;
        int cx = ix + dx - 1, cy = iy + dy - 1, cz = iz + dz - 1;
        if ((unsigned)cx < GD && (unsigned)cy < GD && (unsigned)cz < GD) {
            int c = (cz * GD + cy) * GD + cx;
            int n = min(d_cnt[c], CAP);
            const float4* sp = &d_slot[c * CAP];
            for (int e = 0; e < n; e++) {
                float4 p = sp[e];
                float ddx = p.x - xi;
                float ddy = p.y - yi;
                float ddz = p.z - zi;
                float r2 = fmaf(ddx, ddx, fmaf(ddy, ddy, fmaf(ddz, ddz, EPS)));
                float r;
                asm("sqrt.approx.f32 %0, %1;" : "=f"(r) : "f"(r2));
                float q   = r * INV_H;
                float qm1 = q - 1.0f;
                float wi  = fmaf(q * q * 6.0f, qm1, 1.0f);   // 1 - 6q^2 + 6q^3
                float wo  = -2.0f * qm1 * qm1 * qm1;         // 2(1-q)^3
                float w   = (q <= 0.5f) ? wi : wo;
                acc += (q <= 1.0f) ? w : 0.0f;
            }
        }
    }

    // full-warp reduction
    #pragma unroll
    for (int off = 16; off > 0; off >>= 1)
        acc += __shfl_xor_sync(0xFFFFFFFFu, acc, off);

    if (lane == 0) out[i] = acc * kNorm;
}

extern "C" void kernel_launch(void* const* d_in, const int* in_sizes, int n_in,
                              void* d_out, int out_size)
{
    const float* pos = (const float*)d_in[0];
    float* out = (float*)d_out;
    (void)in_sizes; (void)n_in; (void)out_size;

    zero_cnt_kernel<<<NCELLS / 4 / 256, 256>>>();          // 108 blocks
    build_kernel<<<NP / 256, 256>>>(pos);                  // 32 blocks
    query_kernel<<<NP * 32 / 256, 256>>>(pos, out);        // 1024 blocks
}